// round 3
// baseline (speedup 1.0000x reference)
#include <cuda_runtime.h>
#include <cstdint>

// Problem dims (fixed by the reference)
static constexpr int M = 8192;
static constexpr int N = 4096;
static constexpr int K = 4096;

// Tiling
static constexpr int BM = 128;
static constexpr int BN = 128;
static constexpr int BK = 64;
static constexpr int LDSS = 80;         // smem row stride in bytes (64 data + 16 pad)
static constexpr int KT = K / BK;       // 64 k-tiles

// int8 scratch (pre-quantized inputs). __device__ globals are the allowed scratch path.
__device__ int8_t g_xq[(size_t)M * K];   // 32 MB
__device__ int8_t g_wq[(size_t)N * K];   // 16 MB

// ---------------------------------------------------------------------------
// Pre-pass: canonicalized input (f32 or i32 words, integer values in [-128,127])
// -> packed int8. Dtype-agnostic per-word decode:
//   word as int32 in [-128,127]  -> int32 payload, take it
//   else                         -> float payload, round-to-nearest-even
// ---------------------------------------------------------------------------
__device__ __forceinline__ int8_t decode_q(uint32_t bits) {
    int iv = (int)bits;
    if ((unsigned)(iv + 128) <= 255u) return (int8_t)iv;
    float f = __int_as_float((int)bits);
    int v = __float2int_rn(f);
    v = min(127, max(-128, v));
    return (int8_t)v;
}

__global__ void quantize_kernel(const uint32_t* __restrict__ in,
                                int8_t* __restrict__ out, int n4)
{
    int i = blockIdx.x * blockDim.x + threadIdx.x;
    if (i < n4) {
        uint4 v = ((const uint4*)in)[i];
        char4 o;
        o.x = decode_q(v.x);
        o.y = decode_q(v.y);
        o.z = decode_q(v.z);
        o.w = decode_q(v.w);
        ((char4*)out)[i] = o;
    }
}

// ---------------------------------------------------------------------------
// int8 GEMM: C[m,n] = sum_k A[m,k] * B[n,k], fused dequant/requant epilogue.
// ---------------------------------------------------------------------------
__device__ __forceinline__ void cp_async16(void* smem_dst, const void* gmem_src) {
    uint32_t s = (uint32_t)__cvta_generic_to_shared(smem_dst);
    asm volatile("cp.async.cg.shared.global [%0], [%1], 16;\n" :: "r"(s), "l"(gmem_src));
}
__device__ __forceinline__ void cp_async_commit() {
    asm volatile("cp.async.commit_group;\n");
}
template <int NN>
__device__ __forceinline__ void cp_async_wait() {
    asm volatile("cp.async.wait_group %0;\n" :: "n"(NN));
}

__device__ __forceinline__ void mma_s8(int32_t* c, const uint32_t* a, const uint32_t* b) {
    asm volatile(
        "mma.sync.aligned.m16n8k32.row.col.s32.s8.s8.s32 "
        "{%0,%1,%2,%3}, {%4,%5,%6,%7}, {%8,%9}, {%0,%1,%2,%3};\n"
        : "+r"(c[0]), "+r"(c[1]), "+r"(c[2]), "+r"(c[3])
        : "r"(a[0]), "r"(a[1]), "r"(a[2]), "r"(a[3]),
          "r"(b[0]), "r"(b[1]));
}

__global__ __launch_bounds__(256, 2)
void int8_gemm_kernel(const float* __restrict__ scale_x,
                      const float* __restrict__ w_scale,
                      const float* __restrict__ o_scale,
                      float* __restrict__ C)             // [M, N] float32 output
{
    const int8_t* __restrict__ A = g_xq;
    const int8_t* __restrict__ B = g_wq;

    __shared__ int8_t smA[2][BM * LDSS];
    __shared__ int8_t smB[2][BN * LDSS];

    const int tid  = threadIdx.x;
    const int warp = tid >> 5;
    const int lane = tid & 31;
    const int warpM = warp >> 1;      // 0..3 -> 32-row slab
    const int warpN = warp & 1;       // 0..1 -> 64-col slab
    const int g = lane >> 2;          // group id 0..7
    const int q = lane & 3;           // thread-in-group 0..3

    const int bm = blockIdx.y * BM;
    const int bn = blockIdx.x * BN;

    // cp.async mapping: tile = 128 rows x 64B = 512 x 16B chunks; 2 chunks/thread.
    const int ch0 = tid;
    const int ch1 = tid + 256;
    const int r0 = ch0 >> 2, col0 = (ch0 & 3) * 16;
    const int r1 = ch1 >> 2, col1 = (ch1 & 3) * 16;

    auto load_tile = [&](int stage, int kt) {
        const int k0 = kt * BK;
        cp_async16(&smA[stage][r0 * LDSS + col0], A + (size_t)(bm + r0) * K + k0 + col0);
        cp_async16(&smA[stage][r1 * LDSS + col1], A + (size_t)(bm + r1) * K + k0 + col1);
        cp_async16(&smB[stage][r0 * LDSS + col0], B + (size_t)(bn + r0) * K + k0 + col0);
        cp_async16(&smB[stage][r1 * LDSS + col1], B + (size_t)(bn + r1) * K + k0 + col1);
        cp_async_commit();
    };

    int32_t acc[2][8][4];
    #pragma unroll
    for (int mt = 0; mt < 2; mt++)
        #pragma unroll
        for (int nt = 0; nt < 8; nt++)
            #pragma unroll
            for (int i = 0; i < 4; i++)
                acc[mt][nt][i] = 0;

    // Prologue
    load_tile(0, 0);

    for (int kt = 0; kt < KT; kt++) {
        if (kt + 1 < KT) {
            load_tile((kt + 1) & 1, kt + 1);
            cp_async_wait<1>();
        } else {
            cp_async_wait<0>();
        }
        __syncthreads();

        const int st = kt & 1;
        #pragma unroll
        for (int ki = 0; ki < 2; ki++) {        // two k32 steps inside BK=64
            const int kc = ki * 32 + q * 4;

            // A fragments: 2 m-tiles
            uint32_t af[2][4];
            #pragma unroll
            for (int mt = 0; mt < 2; mt++) {
                const int row = warpM * 32 + mt * 16 + g;
                const int8_t* base = &smA[st][row * LDSS + kc];
                af[mt][0] = *(const uint32_t*)(base);                 // (row,   kc)
                af[mt][1] = *(const uint32_t*)(base + 8 * LDSS);      // (row+8, kc)
                af[mt][2] = *(const uint32_t*)(base + 16);            // (row,   kc+16)
                af[mt][3] = *(const uint32_t*)(base + 8 * LDSS + 16); // (row+8, kc+16)
            }
            // B fragments: 8 n-tiles
            uint32_t bf[8][2];
            #pragma unroll
            for (int nt = 0; nt < 8; nt++) {
                const int nrow = warpN * 64 + nt * 8 + g;
                const int8_t* base = &smB[st][nrow * LDSS + kc];
                bf[nt][0] = *(const uint32_t*)(base);
                bf[nt][1] = *(const uint32_t*)(base + 16);
            }
            #pragma unroll
            for (int mt = 0; mt < 2; mt++)
                #pragma unroll
                for (int nt = 0; nt < 8; nt++)
                    mma_s8(acc[mt][nt], af[mt], bf[nt]);
        }
        __syncthreads();
    }

    // Epilogue: dequant -> round-nearest-even -> clamp -> store quantized value AS FLOAT
    const float scale = scale_x[0] * w_scale[0] / o_scale[0];

    #pragma unroll
    for (int mt = 0; mt < 2; mt++) {
        #pragma unroll
        for (int nt = 0; nt < 8; nt++) {
            const int row0 = bm + warpM * 32 + mt * 16 + g;
            const int col  = bn + warpN * 64 + nt * 8 + q * 2;
            #pragma unroll
            for (int half = 0; half < 2; half++) {
                const int row = row0 + half * 8;
                int v0 = __float2int_rn((float)acc[mt][nt][half * 2 + 0] * scale);
                int v1 = __float2int_rn((float)acc[mt][nt][half * 2 + 1] * scale);
                v0 = min(127, max(-128, v0));
                v1 = min(127, max(-128, v1));
                float2 out;
                out.x = (float)v0;
                out.y = (float)v1;
                *(float2*)(C + (size_t)row * N + col) = out;
            }
        }
    }
}

// Fill any trailing elements beyond M*N (packed tuple output: out_scale as float).
__global__ void tail_fill_kernel(float* __restrict__ out, int start, int total,
                                 const float* __restrict__ o_scale)
{
    int idx = start + blockIdx.x * blockDim.x + threadIdx.x;
    if (idx < total) {
        out[idx] = o_scale[0];
    }
}

extern "C" void kernel_launch(void* const* d_in, const int* in_sizes, int n_in,
                              void* d_out, int out_size)
{
    // Identify inputs by element count (robust to metadata ordering).
    const void* x_ptr = nullptr;
    const void* w_ptr = nullptr;
    const float* scalars[3] = {nullptr, nullptr, nullptr};
    int ns = 0;
    for (int i = 0; i < n_in; i++) {
        long long sz = in_sizes[i];
        if (sz == (long long)M * K)      x_ptr = d_in[i];
        else if (sz == (long long)N * K) w_ptr = d_in[i];
        else if (ns < 3)                 scalars[ns++] = (const float*)d_in[i];
    }
    const float* scale_x = scalars[0];   // relative order: scale_x, weight_scale, out_scale
    const float* w_scale = scalars[1];
    const float* o_scale = scalars[2];
    float* out = (float*)d_out;

    int8_t* xq_dev;
    int8_t* wq_dev;
    cudaGetSymbolAddress((void**)&xq_dev, g_xq);
    cudaGetSymbolAddress((void**)&wq_dev, g_wq);

    // Pre-pass: decode canonicalized inputs to packed int8 scratch.
    {
        int n4 = (M * K) / 4;
        quantize_kernel<<<(n4 + 255) / 256, 256>>>((const uint32_t*)x_ptr, xq_dev, n4);
        n4 = (N * K) / 4;
        quantize_kernel<<<(n4 + 255) / 256, 256>>>((const uint32_t*)w_ptr, wq_dev, n4);
    }

    dim3 grid(N / BN, M / BM);   // (32, 64)
    dim3 block(256);
    int8_gemm_kernel<<<grid, block>>>(scale_x, w_scale, o_scale, out);

    const long long body = (long long)M * N;
    if ((long long)out_size > body) {
        long long extra = out_size - body;
        tail_fill_kernel<<<(int)((extra + 255) / 256), 256>>>(out, (int)body, out_size, o_scale);
    }
}